// round 4
// baseline (speedup 1.0000x reference)
#include <cuda_runtime.h>

typedef unsigned long long u64;

#define H_      51
#define TSTEPS  512
#define BTOT    1024
#define NB      8                 // batch rows per block
#define NBLK    (BTOT / NB)       // 128 blocks
#define NTHR    256
#define GP_     224               // padded gate count (204 -> 224 = 7*32)
#define L1K4    13                // layer1 K: 52 -> 13 float4 chunks
#define L2K4    26                // layer2 K: 104 -> 26 float4 chunks
#define HROW    108               // floats per batch h-row: [h1(51)|pad|h2(51)|pad]
#define PR1     228               // partial-gate row stride per batch (228 % 32 == 4)
#define PR2     (NB * PR1)        // per-kh partial block

// ---- shared memory layout (float offsets, 16B aligned where needed) ----
#define OFF_W1   0                          // [13][224][4]
#define OFF_W2   (OFF_W1 + L1K4*GP_*4)      // [26][224][4]
#define OFF_XS   (OFF_W2 + L2K4*GP_*4)      // [512][8]
#define OFF_HS   (OFF_XS + TSTEPS*NB)       // [8][108]
#define OFF_C1   (OFF_HS + NB*HROW)         // [8][52]
#define OFF_C2   (OFF_C1 + NB*52)           // [8][52]
#define OFF_PB   (OFF_C2 + NB*52)           // [8 kh][8 b][228]
#define OFF_B1   (OFF_PB + 8*PR2)           // 224
#define OFF_B2   (OFF_B1 + GP_)             // 224
#define OFF_WI1  (OFF_B2 + GP_)             // 224
#define OFF_WL   (OFF_WI1 + GP_)            // 52
#define OFF_BL   (OFF_WL + 52)              // 4
#define SMEM_FLOATS (OFF_BL + 4)
#define SMEM_BYTES  (SMEM_FLOATS * 4)       // ~219 KB

__device__ __forceinline__ void ffma2(u64 &d, u64 a, u64 b) {
    asm("fma.rn.f32x2 %0, %1, %2, %0;" : "+l"(d) : "l"(a), "l"(b));
}
__device__ __forceinline__ float2 unpk(u64 v) {
    float2 r;
    asm("mov.b64 {%0, %1}, %2;" : "=f"(r.x), "=f"(r.y) : "l"(v));
    return r;
}
__device__ __forceinline__ float sigf(float x) {
    float e = __expf(-x);
    return 1.0f / (1.0f + e);
}

// gate GEMV: lane = gate slot s (g = s + 32j), warp = k-slice [kqb,kqe).
// Each thread accumulates all 8 batches x 7 gate groups.
// w loads: 16B unique per lane (coalesced 512B); h loads: warp-uniform broadcast.
__device__ __forceinline__ void gate_phase(const float* sm, int lane,
                                           int kqb, int kqe, int woff,
                                           u64 (&acc)[7][8])
{
#pragma unroll
    for (int j = 0; j < 7; j++)
#pragma unroll
        for (int b = 0; b < 8; b++) acc[j][b] = 0ull;

    const ulonglong2* __restrict__ wp =
        reinterpret_cast<const ulonglong2*>(sm + woff) + lane;
    const ulonglong2* __restrict__ hp =
        reinterpret_cast<const ulonglong2*>(sm + OFF_HS);
    for (int kq = kqb; kq < kqe; kq++) {
        ulonglong2 w[7];
#pragma unroll
        for (int j = 0; j < 7; j++) w[j] = wp[kq * GP_ + 32 * j];
#pragma unroll
        for (int b = 0; b < 8; b++) {
            ulonglong2 h = hp[b * (HROW / 4) + kq];
#pragma unroll
            for (int j = 0; j < 7; j++) {
                ffma2(acc[j][b], w[j].x, h.x);
                ffma2(acc[j][b], w[j].y, h.y);
            }
        }
    }
}

// write per-kh partial gate sums; kh0 also folds in the x * W_ih1 term (layer 1)
__device__ __forceinline__ void store_partial(float* sm, int lane, int kh,
                                              u64 (&acc)[7][8],
                                              bool addx, const float* xrow)
{
    float* pb = sm + OFF_PB + kh * PR2 + lane;
    float wi[7];
    if (addx) {
#pragma unroll
        for (int j = 0; j < 7; j++) wi[j] = sm[OFF_WI1 + lane + 32 * j];
    }
#pragma unroll
    for (int b = 0; b < 8; b++) {
        float xv = addx ? xrow[b] : 0.0f;
#pragma unroll
        for (int j = 0; j < 7; j++) {
            float2 p = unpk(acc[j][b]);
            float gv = p.x + p.y;
            if (addx) gv = fmaf(xv, wi[j], gv);
            pb[b * PR1 + 32 * j] = gv;
        }
    }
}

// pointwise cell update: 408 jobs (b, j); sums 8 kh partials + bias
__device__ __forceinline__ void update_phase(float* sm, int tid, int coff,
                                             int hoff, int boff)
{
#pragma unroll
    for (int r = 0; r < 2; r++) {
        int job = tid + r * NTHR;
        if (job < NB * H_) {
            int b = job & 7, j = job >> 3;          // j in 0..50
            float gi = sm[boff + j];
            float gf = sm[boff + 51 + j];
            float gg = sm[boff + 102 + j];
            float go = sm[boff + 153 + j];
            const float* pb = sm + OFF_PB + b * PR1 + j;
#pragma unroll
            for (int kh = 0; kh < 8; kh++) {
                const float* p = pb + kh * PR2;
                gi += p[0];
                gf += p[51];
                gg += p[102];
                go += p[153];
            }
            float c  = sm[coff + b * 52 + j];
            float cn = sigf(gf) * c + sigf(gi) * tanhf(gg);
            float hn = sigf(go) * tanhf(cn);
            sm[coff + b * 52 + j] = cn;
            sm[OFF_HS + b * HROW + hoff + j] = hn;
        }
    }
}

__global__ void __launch_bounds__(NTHR, 1)
lstm_kernel(const float* __restrict__ input,
            const float* __restrict__ Wih1, const float* __restrict__ Whh1,
            const float* __restrict__ bih1, const float* __restrict__ bhh1,
            const float* __restrict__ Wih2, const float* __restrict__ Whh2,
            const float* __restrict__ bih2, const float* __restrict__ bhh2,
            const float* __restrict__ Wlin, const float* __restrict__ blin,
            float* __restrict__ out)
{
    extern __shared__ float sm[];
    const int tid  = threadIdx.x;
    const int bid  = blockIdx.x;
    const int lane = tid & 31;
    const int kh   = tid >> 5;            // warp id = k-slice 0..7

    // ---- staging ----
    for (int i = tid; i < NB * HROW; i += NTHR) sm[OFF_HS + i] = 0.0f;
    for (int i = tid; i < NB * 52 * 2; i += NTHR) sm[OFF_C1 + i] = 0.0f;

    for (int i = tid; i < TSTEPS * NB; i += NTHR) {
        int t = i >> 3, bb = i & 7;
        sm[OFF_XS + i] = input[t * BTOT + bid * NB + bb];
    }
    // W1: W_hh1, k-packed [kq][g][4]
    for (int i = tid; i < L1K4 * GP_ * 4; i += NTHR) {
        int c = i & 3, g = (i >> 2) % GP_, kq = i / (GP_ * 4);
        int k = 4 * kq + c;
        sm[OFF_W1 + i] = (g < 204 && k < H_) ? Whh1[g * H_ + k] : 0.0f;
    }
    // W2: concat [W_ih2 (k 0..50) | pad(51) | W_hh2 (k 52..102) | pad(103)]
    for (int i = tid; i < L2K4 * GP_ * 4; i += NTHR) {
        int c = i & 3, g = (i >> 2) % GP_, kq = i / (GP_ * 4);
        int k = 4 * kq + c;
        float v = 0.0f;
        if (g < 204) {
            if (k < H_)                  v = Wih2[g * H_ + k];
            else if (k >= 52 && k < 103) v = Whh2[g * H_ + (k - 52)];
        }
        sm[OFF_W2 + i] = v;
    }
    for (int i = tid; i < GP_; i += NTHR) {
        sm[OFF_B1  + i] = (i < 204) ? bih1[i] + bhh1[i] : 0.0f;
        sm[OFF_B2  + i] = (i < 204) ? bih2[i] + bhh2[i] : 0.0f;
        sm[OFF_WI1 + i] = (i < 204) ? Wih1[i] : 0.0f;
    }
    if (tid < 52) sm[OFF_WL + tid] = (tid < H_) ? Wlin[tid] : 0.0f;
    if (tid == 0) sm[OFF_BL] = blin[0];
    __syncthreads();

    // per-kh k-chunk ranges (kh0 lighter: it also does the x term)
    const int l1kqb[8] = {0, 1, 3, 5, 7, 9, 11, 12};
    const int l1kqe[8] = {1, 3, 5, 7, 9, 11, 12, 13};
    const int l2kqb[8] = {0, 3, 7, 11, 14, 17, 20, 23};
    const int l2kqe[8] = {3, 7, 11, 14, 17, 20, 23, 26};
    const int a1 = l1kqb[kh], e1 = l1kqe[kh];
    const int a2 = l2kqb[kh], e2 = l2kqe[kh];

    u64 acc[7][8];

    // ---- recurrence ----
    for (int t = 0; t < TSTEPS; t++) {
        // layer 1 gates (reads h1 at HS k=0..51)
        gate_phase(sm, lane, a1, e1, OFF_W1, acc);
        store_partial(sm, lane, kh, acc, kh == 0, sm + OFF_XS + t * NB);
        __syncthreads();
        update_phase(sm, tid, OFF_C1, 0, OFF_B1);
        __syncthreads();

        // layer 2 gates (reads concat(h1|h2) at HS k=0..103)
        gate_phase(sm, lane, a2, e2, OFF_W2, acc);
        store_partial(sm, lane, kh, acc, false, nullptr);
        __syncthreads();
        update_phase(sm, tid, OFF_C2, 52, OFF_B2);
        __syncthreads();

        // output: out[b_global][t] = h2 . Wlin + blin  (warp 0 only)
        if (tid < 32) {
            int ob = tid & 7, part = tid >> 3;     // 4 parts x 13 k
            float a = 0.0f;
#pragma unroll
            for (int kk = 0; kk < 13; kk++) {
                int k = part * 13 + kk;            // k max 51 -> zero pad
                a = fmaf(sm[OFF_HS + ob * HROW + 52 + k], sm[OFF_WL + k], a);
            }
            a += __shfl_xor_sync(0xffffffffu, a, 8);
            a += __shfl_xor_sync(0xffffffffu, a, 16);
            if (tid < 8)
                out[(bid * NB + ob) * TSTEPS + t] = a + sm[OFF_BL];
        }
    }
}

extern "C" void kernel_launch(void* const* d_in, const int* in_sizes, int n_in,
                              void* d_out, int out_size)
{
    const float* input = (const float*)d_in[0];
    const float* Wih1  = (const float*)d_in[1];
    const float* Whh1  = (const float*)d_in[2];
    const float* bih1  = (const float*)d_in[3];
    const float* bhh1  = (const float*)d_in[4];
    const float* Wih2  = (const float*)d_in[5];
    const float* Whh2  = (const float*)d_in[6];
    const float* bih2  = (const float*)d_in[7];
    const float* bhh2  = (const float*)d_in[8];
    const float* Wlin  = (const float*)d_in[9];
    const float* blin  = (const float*)d_in[10];
    float* out = (float*)d_out;

    cudaFuncSetAttribute(lstm_kernel,
                         cudaFuncAttributeMaxDynamicSharedMemorySize,
                         SMEM_BYTES);
    lstm_kernel<<<NBLK, NTHR, SMEM_BYTES>>>(input, Wih1, Whh1, bih1, bhh1,
                                            Wih2, Whh2, bih2, bhh2,
                                            Wlin, blin, out);
}

// round 5
// speedup vs baseline: 1.2693x; 1.2693x over previous
#include <cuda_runtime.h>

typedef unsigned long long u64;

#define H_      51
#define TSTEPS  512
#define BTOT    1024
#define NB      8                 // batch rows per block
#define NBLK    (BTOT / NB)       // 128 blocks
#define NTHR    512
#define GP_     224               // padded gate count (204 -> 224 = 7*32)
#define L1K4    13                // layer1 K: 52 -> 13 float4 chunks
#define L2K4    26                // layer2 K: 104 -> 26 float4 chunks
#define HROW    108               // h row: [h1(51)|pad|h2(51)|pad..] (27 u64x2)
#define HC      (HROW/4)          // 27 ulonglong2 per h row
#define PR1     228               // partial row stride per batch
#define PR2     (NB * PR1)        // per-kh partial block (1824)

// ---- shared memory layout (float offsets) ----
#define OFF_W1   0                          // [13][224][4]
#define OFF_W2   (OFF_W1 + L1K4*GP_*4)      // [26][224][4]
#define OFF_XS   (OFF_W2 + L2K4*GP_*4)      // [512][8]
#define OFF_HS   (OFF_XS + TSTEPS*NB)       // [8][108]
#define OFF_C1   (OFF_HS + NB*HROW)         // [8][52]
#define OFF_C2   (OFF_C1 + NB*52)           // [8][52]
#define OFF_PB   (OFF_C2 + NB*52)           // [8 kh][8 b][228]
#define OFF_B1   (OFF_PB + 8*PR2)           // 224
#define OFF_B2   (OFF_B1 + GP_)             // 224
#define OFF_WI1  (OFF_B2 + GP_)             // 224
#define OFF_WL   (OFF_WI1 + GP_)            // 52
#define OFF_BL   (OFF_WL + 52)              // 4
#define SMEM_FLOATS (OFF_BL + 4)
#define SMEM_BYTES  (SMEM_FLOATS * 4)       // ~224.5 KB

__device__ __forceinline__ void ffma2(u64 &d, u64 a, u64 b) {
    asm("fma.rn.f32x2 %0, %1, %2, %0;" : "+l"(d) : "l"(a), "l"(b));
}
__device__ __forceinline__ float2 unpk(u64 v) {
    float2 r;
    asm("mov.b64 {%0, %1}, %2;" : "=f"(r.x), "=f"(r.y) : "l"(v));
    return r;
}
// fast sigmoid / tanh: 1 EX2 + 1 RCP each, error ~1e-7 rel. Saturates
// correctly at +/-inf (exp -> inf -> rcp -> 0).
__device__ __forceinline__ float sigf(float x) {
    return __fdividef(1.0f, 1.0f + __expf(-x));
}
__device__ __forceinline__ float tanhfast(float x) {
    return __fdividef(2.0f, 1.0f + __expf(-2.0f * x)) - 1.0f;
}

// gate GEMV over NKQ static k-chunks: lane = gate slot (g = lane + 32j),
// this warp covers batches bh*4..bh*4+3. w loads coalesced/conflict-free,
// h loads warp-uniform broadcast.
template<int NKQ>
__device__ __forceinline__ void gate_gemv(const ulonglong2* __restrict__ wp,
                                          const ulonglong2* __restrict__ hp,
                                          u64 (&acc)[7][4])
{
#pragma unroll
    for (int j = 0; j < 7; j++)
#pragma unroll
        for (int b = 0; b < 4; b++) acc[j][b] = 0ull;
#pragma unroll
    for (int i = 0; i < NKQ; i++) {
        ulonglong2 h[4];
#pragma unroll
        for (int b = 0; b < 4; b++) h[b] = hp[b * HC + i];
#pragma unroll
        for (int j = 0; j < 7; j++) {
            ulonglong2 w = wp[i * GP_ + 32 * j];
#pragma unroll
            for (int b = 0; b < 4; b++) {
                ffma2(acc[j][b], w.x, h[b].x);
                ffma2(acc[j][b], w.y, h[b].y);
            }
        }
    }
}

// write per-kh partial sums; kh==0 warps fold in the x * W_ih1 term
__device__ __forceinline__ void store_partial(float* __restrict__ pb,
                                              const float* __restrict__ sm,
                                              int lane, int bh,
                                              u64 (&acc)[7][4],
                                              bool addx, const float* xrow)
{
    float wi[7];
    if (addx) {
#pragma unroll
        for (int j = 0; j < 7; j++) wi[j] = sm[OFF_WI1 + lane + 32 * j];
    }
#pragma unroll
    for (int b = 0; b < 4; b++) {
        float xv = addx ? xrow[bh * 4 + b] : 0.0f;
#pragma unroll
        for (int j = 0; j < 7; j++) {
            float2 p = unpk(acc[j][b]);
            float gv = p.x + p.y;
            if (addx) gv = fmaf(xv, wi[j], gv);
            pb[(bh * 4 + b) * PR1 + 32 * j] = gv;
        }
    }
}

// pointwise cell update: 408 jobs (single round at 512 thr); sums 8 kh partials
__device__ __forceinline__ void update_phase(float* sm, int tid, int coff,
                                             int hoff, int boff)
{
    if (tid < NB * H_) {
        int b = tid & 7, j = tid >> 3;              // j in 0..50
        float gi = sm[boff + j];
        float gf = sm[boff + 51 + j];
        float gg = sm[boff + 102 + j];
        float go = sm[boff + 153 + j];
        const float* pb = sm + OFF_PB + b * PR1 + j;
#pragma unroll
        for (int kh = 0; kh < 8; kh++) {
            const float* p = pb + kh * PR2;
            gi += p[0];
            gf += p[51];
            gg += p[102];
            go += p[153];
        }
        float c  = sm[coff + b * 52 + j];
        float cn = sigf(gf) * c + sigf(gi) * tanhfast(gg);
        float hn = sigf(go) * tanhfast(cn);
        sm[coff + b * 52 + j] = cn;
        sm[OFF_HS + b * HROW + hoff + j] = hn;
    }
}

__global__ void __launch_bounds__(NTHR, 1)
lstm_kernel(const float* __restrict__ input,
            const float* __restrict__ Wih1, const float* __restrict__ Whh1,
            const float* __restrict__ bih1, const float* __restrict__ bhh1,
            const float* __restrict__ Wih2, const float* __restrict__ Whh2,
            const float* __restrict__ bih2, const float* __restrict__ bhh2,
            const float* __restrict__ Wlin, const float* __restrict__ blin,
            float* __restrict__ out)
{
    extern __shared__ float sm[];
    const int tid  = threadIdx.x;
    const int bid  = blockIdx.x;
    const int lane = tid & 31;
    const int wid  = tid >> 5;            // 0..15
    const int kh   = wid >> 1;            // k-slice 0..7
    const int bh   = wid & 1;             // batch half 0/1

    // ---- staging ----
    for (int i = tid; i < NB * HROW; i += NTHR) sm[OFF_HS + i] = 0.0f;
    for (int i = tid; i < NB * 52 * 2; i += NTHR) sm[OFF_C1 + i] = 0.0f;

    for (int i = tid; i < TSTEPS * NB; i += NTHR) {
        int t = i >> 3, bb = i & 7;
        sm[OFF_XS + i] = input[t * BTOT + bid * NB + bb];
    }
    // W1: W_hh1, k-packed [kq][g][4]
    for (int i = tid; i < L1K4 * GP_ * 4; i += NTHR) {
        int c = i & 3, g = (i >> 2) % GP_, kq = i / (GP_ * 4);
        int k = 4 * kq + c;
        sm[OFF_W1 + i] = (g < 204 && k < H_) ? Whh1[g * H_ + k] : 0.0f;
    }
    // W2: concat [W_ih2 (k 0..50) | pad(51) | W_hh2 (k 52..102) | pad(103)]
    for (int i = tid; i < L2K4 * GP_ * 4; i += NTHR) {
        int c = i & 3, g = (i >> 2) % GP_, kq = i / (GP_ * 4);
        int k = 4 * kq + c;
        float v = 0.0f;
        if (g < 204) {
            if (k < H_)                  v = Wih2[g * H_ + k];
            else if (k >= 52 && k < 103) v = Whh2[g * H_ + (k - 52)];
        }
        sm[OFF_W2 + i] = v;
    }
    for (int i = tid; i < GP_; i += NTHR) {
        sm[OFF_B1  + i] = (i < 204) ? bih1[i] + bhh1[i] : 0.0f;
        sm[OFF_B2  + i] = (i < 204) ? bih2[i] + bhh2[i] : 0.0f;
        sm[OFF_WI1 + i] = (i < 204) ? Wih1[i] : 0.0f;
    }
    if (tid < 52) sm[OFF_WL + tid] = (tid < H_) ? Wlin[tid] : 0.0f;
    if (tid == 0) sm[OFF_BL] = blin[0];
    __syncthreads();

    // per-warp static k-slices: L1 13 = 5x2 + 3x1 ; L2 26 = 2x4 + 6x3
    const int l1s = (kh < 5) ? 2 * kh : 10 + (kh - 5);
    const int l2s = (kh < 2) ? 4 * kh : 8 + 3 * (kh - 2);

    const ulonglong2* __restrict__ wp1 =
        reinterpret_cast<const ulonglong2*>(sm + OFF_W1) + l1s * GP_ + lane;
    const ulonglong2* __restrict__ wp2 =
        reinterpret_cast<const ulonglong2*>(sm + OFF_W2) + l2s * GP_ + lane;
    const ulonglong2* __restrict__ hp1 =
        reinterpret_cast<const ulonglong2*>(sm + OFF_HS) + bh * 4 * HC + l1s;
    const ulonglong2* __restrict__ hp2 =
        reinterpret_cast<const ulonglong2*>(sm + OFF_HS) + bh * 4 * HC + l2s;
    float* pb = sm + OFF_PB + kh * PR2 + lane;

    u64 acc[7][4];

    // ---- recurrence ----
    for (int t = 0; t < TSTEPS; t++) {
        // layer 1 gates (reads h1 at HS k = 0..51)
        if (kh < 5) gate_gemv<2>(wp1, hp1, acc);
        else        gate_gemv<1>(wp1, hp1, acc);
        store_partial(pb, sm, lane, bh, acc, kh == 0, sm + OFF_XS + t * NB);
        __syncthreads();
        update_phase(sm, tid, OFF_C1, 0, OFF_B1);
        __syncthreads();

        // layer 2 gates (reads concat(h1|h2) at HS k = 0..103)
        if (kh < 2) gate_gemv<4>(wp2, hp2, acc);
        else        gate_gemv<3>(wp2, hp2, acc);
        store_partial(pb, sm, lane, bh, acc, false, nullptr);
        __syncthreads();
        update_phase(sm, tid, OFF_C2, 52, OFF_B2);
        __syncthreads();

        // output: out[b_global][t] = h2 . Wlin + blin  (warp 0 only)
        if (tid < 32) {
            int ob = tid & 7, part = tid >> 3;     // 4 parts x 13 k
            float a = 0.0f;
#pragma unroll
            for (int kk = 0; kk < 13; kk++) {
                int k = part * 13 + kk;            // k max 51 -> zero pad
                a = fmaf(sm[OFF_HS + ob * HROW + 52 + k], sm[OFF_WL + k], a);
            }
            a += __shfl_xor_sync(0xffffffffu, a, 8);
            a += __shfl_xor_sync(0xffffffffu, a, 16);
            if (tid < 8)
                out[(bid * NB + ob) * TSTEPS + t] = a + sm[OFF_BL];
        }
    }
}

extern "C" void kernel_launch(void* const* d_in, const int* in_sizes, int n_in,
                              void* d_out, int out_size)
{
    const float* input = (const float*)d_in[0];
    const float* Wih1  = (const float*)d_in[1];
    const float* Whh1  = (const float*)d_in[2];
    const float* bih1  = (const float*)d_in[3];
    const float* bhh1  = (const float*)d_in[4];
    const float* Wih2  = (const float*)d_in[5];
    const float* Whh2  = (const float*)d_in[6];
    const float* bih2  = (const float*)d_in[7];
    const float* bhh2  = (const float*)d_in[8];
    const float* Wlin  = (const float*)d_in[9];
    const float* blin  = (const float*)d_in[10];
    float* out = (float*)d_out;

    static bool attr_set = false;
    if (!attr_set) {
        cudaFuncSetAttribute(lstm_kernel,
                             cudaFuncAttributeMaxDynamicSharedMemorySize,
                             SMEM_BYTES);
        attr_set = true;
    }
    lstm_kernel<<<NBLK, NTHR, SMEM_BYTES>>>(input, Wih1, Whh1, bih1, bhh1,
                                            Wih2, Whh2, bih2, bhh2,
                                            Wlin, blin, out);
}

// round 6
// speedup vs baseline: 1.6377x; 1.2903x over previous
#include <cuda_runtime.h>

typedef unsigned long long u64;

#define H_      51
#define TSTEPS  512
#define BTOT    1024
#define NB      8                 // batch rows per block
#define NBLK    (BTOT / NB)       // 128 blocks
#define NTHR    512
#define GP_     224               // padded gate count (204 -> 224 = 7*32)
#define L1K4    13                // layer1 K: 52 -> 13 float4 chunks
#define L2K4    26                // layer2 K: 104 -> 26 float4 chunks
#define HROW    108               // h row: [h1(51)|pad|h2(51)|pad..]
#define HC      (HROW/4)          // 27 ulonglong2 per h row
#define PR1     228               // partial row stride per batch
#define PR2     (NB * PR1)        // per-level partial block (1824)
#define L1KH    3                 // layer1 k-levels
#define L2KH    5                 // layer2 k-levels

// ---- shared memory layout (float offsets) ----
#define OFF_W1   0                          // [13][224][4]
#define OFF_W2   (OFF_W1 + L1K4*GP_*4)      // [26][224][4]
#define OFF_XS   (OFF_W2 + L2K4*GP_*4)      // [512][8]
#define OFF_HS   (OFF_XS + TSTEPS*NB)       // [8][108]
#define OFF_C1   (OFF_HS + NB*HROW)         // [8][52]
#define OFF_C2   (OFF_C1 + NB*52)           // [8][52]
#define OFF_PB   (OFF_C2 + NB*52)           // [8 levels][8 b][228]: 3 L1 + 5 L2
#define OFF_PB2  (OFF_PB + L1KH*PR2)
#define OFF_B1   (OFF_PB + 8*PR2)           // 224
#define OFF_B2   (OFF_B1 + GP_)             // 224
#define OFF_WI1  (OFF_B2 + GP_)             // 224
#define OFF_WL   (OFF_WI1 + GP_)            // 52
#define OFF_BL   (OFF_WL + 52)              // 4
#define SMEM_FLOATS (OFF_BL + 4)
#define SMEM_BYTES  (SMEM_FLOATS * 4)       // ~224.5 KB

__device__ __forceinline__ void ffma2(u64 &d, u64 a, u64 b) {
    asm("fma.rn.f32x2 %0, %1, %2, %0;" : "+l"(d) : "l"(a), "l"(b));
}
__device__ __forceinline__ float2 unpk(u64 v) {
    float2 r;
    asm("mov.b64 {%0, %1}, %2;" : "=f"(r.x), "=f"(r.y) : "l"(v));
    return r;
}
__device__ __forceinline__ float sigf(float x) {
    return __fdividef(1.0f, 1.0f + __expf(-x));
}
__device__ __forceinline__ float tanhfast(float x) {
    return __fdividef(2.0f, 1.0f + __expf(-2.0f * x)) - 1.0f;
}

// gate GEMV over NKQ static k-chunks: lane = gate slot (g = lane + 32j),
// warp covers batches bh*4..bh*4+3.
template<int NKQ>
__device__ __forceinline__ void gate_gemv(const ulonglong2* __restrict__ wp,
                                          const ulonglong2* __restrict__ hp,
                                          u64 (&acc)[7][4])
{
#pragma unroll
    for (int j = 0; j < 7; j++)
#pragma unroll
        for (int b = 0; b < 4; b++) acc[j][b] = 0ull;
#pragma unroll
    for (int i = 0; i < NKQ; i++) {
        ulonglong2 h[4];
#pragma unroll
        for (int b = 0; b < 4; b++) h[b] = hp[b * HC + i];
#pragma unroll
        for (int j = 0; j < 7; j++) {
            ulonglong2 w = wp[i * GP_ + 32 * j];
#pragma unroll
            for (int b = 0; b < 4; b++) {
                ffma2(acc[j][b], w.x, h[b].x);
                ffma2(acc[j][b], w.y, h[b].y);
            }
        }
    }
}

__device__ __forceinline__ void store_partial(float* __restrict__ pb,
                                              const float* __restrict__ sm,
                                              int lane, int bh,
                                              u64 (&acc)[7][4],
                                              bool addx, const float* xrow)
{
    float wi[7];
    if (addx) {
#pragma unroll
        for (int j = 0; j < 7; j++) wi[j] = sm[OFF_WI1 + lane + 32 * j];
    }
#pragma unroll
    for (int b = 0; b < 4; b++) {
        float xv = addx ? xrow[bh * 4 + b] : 0.0f;
#pragma unroll
        for (int j = 0; j < 7; j++) {
            float2 p = unpk(acc[j][b]);
            float gv = p.x + p.y;
            if (addx) gv = fmaf(xv, wi[j], gv);
            pb[(bh * 4 + b) * PR1 + 32 * j] = gv;
        }
    }
}

// pointwise cell update: 408 jobs (b, j), sums NLEV partial levels + bias
template<int NLEV>
__device__ __forceinline__ void update_phase(float* sm, int tid, int coff,
                                             int hoff, int boff, int pboff)
{
    if (tid < NB * H_) {
        int b = tid & 7, j = tid >> 3;              // j in 0..50
        float gi = sm[boff + j];
        float gf = sm[boff + 51 + j];
        float gg = sm[boff + 102 + j];
        float go = sm[boff + 153 + j];
        const float* pb = sm + pboff + b * PR1 + j;
#pragma unroll
        for (int l = 0; l < NLEV; l++) {
            const float* p = pb + l * PR2;
            gi += p[0];
            gf += p[51];
            gg += p[102];
            go += p[153];
        }
        float c  = sm[coff + b * 52 + j];
        float cn = sigf(gf) * c + sigf(gi) * tanhfast(gg);
        float hn = sigf(go) * tanhfast(cn);
        sm[coff + b * 52 + j] = cn;
        sm[OFF_HS + b * HROW + hoff + j] = hn;
    }
}

// output dot for step tcol: run by one warp, reads stable h2 in smem
__device__ __forceinline__ void out_phase(const float* sm, int lane, int bid,
                                          int tcol, float* __restrict__ out)
{
    int ob = lane & 7, part = lane >> 3;            // 4 parts x 13 k
    float a = 0.0f;
#pragma unroll
    for (int kk = 0; kk < 13; kk++) {
        int k = part * 13 + kk;                     // k max 51 -> zero pad
        a = fmaf(sm[OFF_HS + ob * HROW + 52 + k], sm[OFF_WL + k], a);
    }
    a += __shfl_xor_sync(0xffffffffu, a, 8);
    a += __shfl_xor_sync(0xffffffffu, a, 16);
    if (lane < 8)
        out[(bid * NB + ob) * TSTEPS + tcol] = a + sm[OFF_BL];
}

__global__ void __launch_bounds__(NTHR, 1)
lstm_kernel(const float* __restrict__ input,
            const float* __restrict__ Wih1, const float* __restrict__ Whh1,
            const float* __restrict__ bih1, const float* __restrict__ bhh1,
            const float* __restrict__ Wih2, const float* __restrict__ Whh2,
            const float* __restrict__ bih2, const float* __restrict__ bhh2,
            const float* __restrict__ Wlin, const float* __restrict__ blin,
            float* __restrict__ out)
{
    extern __shared__ float sm[];
    const int tid  = threadIdx.x;
    const int bid  = blockIdx.x;
    const int lane = tid & 31;
    const int wid  = tid >> 5;            // 0..15

    // ---- staging ----
    for (int i = tid; i < NB * HROW; i += NTHR) sm[OFF_HS + i] = 0.0f;
    for (int i = tid; i < NB * 52 * 2; i += NTHR) sm[OFF_C1 + i] = 0.0f;

    for (int i = tid; i < TSTEPS * NB; i += NTHR) {
        int t = i >> 3, bb = i & 7;
        sm[OFF_XS + i] = input[t * BTOT + bid * NB + bb];
    }
    for (int i = tid; i < L1K4 * GP_ * 4; i += NTHR) {
        int c = i & 3, g = (i >> 2) % GP_, kq = i / (GP_ * 4);
        int k = 4 * kq + c;
        sm[OFF_W1 + i] = (g < 204 && k < H_) ? Whh1[g * H_ + k] : 0.0f;
    }
    for (int i = tid; i < L2K4 * GP_ * 4; i += NTHR) {
        int c = i & 3, g = (i >> 2) % GP_, kq = i / (GP_ * 4);
        int k = 4 * kq + c;
        float v = 0.0f;
        if (g < 204) {
            if (k < H_)                  v = Wih2[g * H_ + k];
            else if (k >= 52 && k < 103) v = Whh2[g * H_ + (k - 52)];
        }
        sm[OFF_W2 + i] = v;
    }
    for (int i = tid; i < GP_; i += NTHR) {
        sm[OFF_B1  + i] = (i < 204) ? bih1[i] + bhh1[i] : 0.0f;
        sm[OFF_B2  + i] = (i < 204) ? bih2[i] + bhh2[i] : 0.0f;
        sm[OFF_WI1 + i] = (i < 204) ? Wih1[i] : 0.0f;
    }
    if (tid < 52) sm[OFF_WL + tid] = (tid < H_) ? Wlin[tid] : 0.0f;
    if (tid == 0) sm[OFF_BL] = blin[0];
    __syncthreads();

    // warp roles:
    //  wid 0..5  : layer-1 warps: kh1 = wid>>1 (0..2), bh = wid&1
    //              kq slices: {0..4}, {5..8}, {9..12}
    //  wid 6..15 : layer-2 warps: kh2 = (wid-6)>>1 (0..4), bh = (wid-6)&1
    //              kq slices: {0..5}, {6..10}, {11..15}, {16..20}, {21..25}
    const bool isL1 = (wid < 6);
    const int  sub  = isL1 ? wid : wid - 6;
    const int  kh   = sub >> 1;
    const int  bh   = sub & 1;

    const int l1start[4] = {0, 5, 9, 13};
    const int l2start[6] = {0, 6, 11, 16, 21, 26};
    const int kstart = isL1 ? l1start[kh] : l2start[kh];

    const ulonglong2* __restrict__ wp =
        reinterpret_cast<const ulonglong2*>(sm + (isL1 ? OFF_W1 : OFF_W2))
        + kstart * GP_ + lane;
    const ulonglong2* __restrict__ hp =
        reinterpret_cast<const ulonglong2*>(sm + OFF_HS) + bh * 4 * HC + kstart;
    float* pb = sm + (isL1 ? OFF_PB : OFF_PB2) + kh * PR2 + lane;

    u64 acc[7][4];

    // ---- prologue: G1(0) ----
    if (isL1) {
        if (kh == 0) gate_gemv<5>(wp, hp, acc);
        else         gate_gemv<4>(wp, hp, acc);
        store_partial(pb, sm, lane, bh, acc, kh == 0, sm + OFF_XS + 0 * NB);
    }
    __syncthreads();
    update_phase<L1KH>(sm, tid, OFF_C1, 0, OFF_B1, OFF_PB);   // U1(0)
    __syncthreads();

    // ---- pipelined recurrence ----
    for (int t = 0; t < TSTEPS; t++) {
        // phase A: G2(t) on L2 warps; G1(t+1) on L1 warps; out(t-1) on warp 4
        if (isL1) {
            if (t + 1 < TSTEPS) {
                if (kh == 0) gate_gemv<5>(wp, hp, acc);
                else         gate_gemv<4>(wp, hp, acc);
                store_partial(pb, sm, lane, bh, acc, kh == 0,
                              sm + OFF_XS + (t + 1) * NB);
            }
            if (wid == 4 && t > 0) out_phase(sm, lane, bid, t - 1, out);
        } else {
            if (kh == 0) gate_gemv<6>(wp, hp, acc);
            else         gate_gemv<5>(wp, hp, acc);
            store_partial(pb, sm, lane, bh, acc, false, nullptr);
        }
        __syncthreads();

        // phase B: U2(t) then U1(t+1)
        update_phase<L2KH>(sm, tid, OFF_C2, 52, OFF_B2, OFF_PB2);
        if (t + 1 < TSTEPS)
            update_phase<L1KH>(sm, tid, OFF_C1, 0, OFF_B1, OFF_PB);
        __syncthreads();
    }

    // ---- epilogue: out(511) ----
    if (wid == 4) out_phase(sm, lane, bid, TSTEPS - 1, out);
}

extern "C" void kernel_launch(void* const* d_in, const int* in_sizes, int n_in,
                              void* d_out, int out_size)
{
    const float* input = (const float*)d_in[0];
    const float* Wih1  = (const float*)d_in[1];
    const float* Whh1  = (const float*)d_in[2];
    const float* bih1  = (const float*)d_in[3];
    const float* bhh1  = (const float*)d_in[4];
    const float* Wih2  = (const float*)d_in[5];
    const float* Whh2  = (const float*)d_in[6];
    const float* bih2  = (const float*)d_in[7];
    const float* bhh2  = (const float*)d_in[8];
    const float* Wlin  = (const float*)d_in[9];
    const float* blin  = (const float*)d_in[10];
    float* out = (float*)d_out;

    static bool attr_set = false;
    if (!attr_set) {
        cudaFuncSetAttribute(lstm_kernel,
                             cudaFuncAttributeMaxDynamicSharedMemorySize,
                             SMEM_BYTES);
        attr_set = true;
    }
    lstm_kernel<<<NBLK, NTHR, SMEM_BYTES>>>(input, Wih1, Whh1, bih1, bhh1,
                                            Wih2, Whh2, bih2, bhh2,
                                            Wlin, blin, out);
}